// round 4
// baseline (speedup 1.0000x reference)
#include <cuda_runtime.h>
#include <math.h>

#define W_IMG 2048
#define H_IMG 2048
#define NPIX (W_IMG * H_IMG)

// scratch (no cudaMalloc allowed)
__device__ float g_tmp[NPIX];     // after horizontal conv, [h][w]

#define DB_SCALE 8.6858896380650365530225783783321f  // 20/ln(10)

// static float constants (match reference float32 math)
#define C_HALF_AX  3.08e-4f
#define C_HALF_LAT 6.16e-4f
#define C_SH       (0.05f / 2048.0f)
#define C_SW       (0.04f / 2048.0f)
#define C_TONE     6.16e-4f
#define C_FWL      3.08e-4f
#define C_PI       3.14159265358979323846f

// ---- packed fp32x2 FMA (Blackwell) ------------------------------------
union F2U { float2 f; unsigned long long u; };

__device__ __forceinline__ float2 ffma2(float2 a, float2 b, float2 c) {
    F2U ua, ub, uc, ud;
    ua.f = a; ub.f = b; uc.f = c;
    asm("fma.rn.f32x2 %0, %1, %2, %3;"
        : "=l"(ud.u) : "l"(ua.u), "l"(ub.u), "l"(uc.u));
    return ud.f;
}

__device__ __forceinline__ int reflect_idx(int x, int n) {
    x = (x < 0) ? -x : x;
    return (x >= n) ? 2 * n - 2 - x : x;
}

// ---------------------------------------------------------------------------
// Kernel 1 (fused): scatterer = exp(raw[...,0]).T, horizontal 61-tap conv
// (reflect) -> g_tmp, scatterers_map = 20*log10(scat+1). Lateral taps are
// computed per-block (cheap float math), normalized by their own sum.
// Tile: 512 (w) x 16 (h) outputs, 512 threads.
// SMEM: row-pairs interleaved -> s[(h>>1)*SROW + p*2 + (h&1)], so the float2
// at (row-pair h2, column p) is an aligned 8B operand for FFMA2.
// ---------------------------------------------------------------------------
#define TW 512
#define TH 16
#define SWT 572           // TW + 60 halo
#define SROW 1146         // 2*SWT + 2 pad -> bank stride 26, conflict-free

__global__ void __launch_bounds__(512)
k1_fused(const float* __restrict__ raw, float* __restrict__ scatmap,
         const float* __restrict__ rl_p) {
    __shared__ float  s[8 * SROW];     // 8 row-pairs x SROW floats (36.7 KB)
    __shared__ float2 sc[64];          // packed lateral taps (c,c), zero-pad
    __shared__ float  tapraw[61];
    __shared__ float  s_inv;

    int w0 = blockIdx.x * TW;
    int h0 = blockIdx.y * TH;
    int tid = threadIdx.x;

    // ---- lateral taps (raw, unnormalized) ----
    if (tid < 61) {
        float rl = rl_p[0];
        float q = ((float)(tid - 30) * (1.0f / 30.0f) * C_HALF_LAT + rl * C_SW)
                  / C_FWL;
        float x = C_PI * q;
        float si = (fabsf(x) < 1e-12f) ? 1.0f : sinf(x) / x;
        tapraw[tid] = si * si;
    }

    // ---- load + exp (implicit transpose): lanes run along h ----
    for (int i = tid; i < SWT * TH; i += 512) {
        int p = i >> 4;                 // tile w index 0..571
        int h = i & 15;                 // local h
        int wg = reflect_idx(w0 + p - 30, W_IMG);
        float v = __expf(raw[((size_t)wg * H_IMG + h0 + h) * 4]);
        s[(h >> 1) * SROW + p * 2 + (h & 1)] = v;
    }
    __syncthreads();

    if (tid == 0) {
        float sl = 0.f;
        for (int j = 0; j < 61; j++) sl += tapraw[j];
        s_inv = 1.0f / sl;
    }
    __syncthreads();
    if (tid < 64) {
        float c = (tid < 61) ? tapraw[tid] * s_inv : 0.f;
        sc[tid] = make_float2(c, c);
    }
    __syncthreads();

    // ---- compute: thread -> (h-pair h2 = tid&7, w group wg = tid>>3) ----
    int h2 = tid & 7;
    int wg = tid >> 3;
    const float2* rowp = (const float2*)(s + h2 * SROW);
    int base = wg * 8;

    float2 win[8], acc[8];
#pragma unroll
    for (int j = 0; j < 8; j++) {
        win[j] = rowp[base + j];
        acc[j] = make_float2(0.f, 0.f);
    }
#pragma unroll
    for (int k = 0; k < 61; k++) {
        float2 cp = sc[k];
#pragma unroll
        for (int j = 0; j < 8; j++) acc[j] = ffma2(cp, win[j], acc[j]);
        if (k < 60) {
#pragma unroll
            for (int j = 0; j < 7; j++) win[j] = win[j + 1];
            win[7] = rowp[base + k + 8];   // max idx 572 < 573, safe
        }
    }

    // ---- stores: conv result (2 rows x 8 cols), then scatmap ----
    int r0 = h0 + 2 * h2;
    int c0 = w0 + base;
    float* t0 = g_tmp + (size_t)r0 * W_IMG + c0;
    float* t1 = t0 + W_IMG;
    ((float4*)t0)[0] = make_float4(acc[0].x, acc[1].x, acc[2].x, acc[3].x);
    ((float4*)t0)[1] = make_float4(acc[4].x, acc[5].x, acc[6].x, acc[7].x);
    ((float4*)t1)[0] = make_float4(acc[0].y, acc[1].y, acc[2].y, acc[3].y);
    ((float4*)t1)[1] = make_float4(acc[4].y, acc[5].y, acc[6].y, acc[7].y);

    // scatterer at output column c = smem float2 index base+j+30
    float l0[8], l1[8];
#pragma unroll
    for (int j = 0; j < 8; j++) {
        float2 sv = rowp[base + j + 30];
        l0[j] = DB_SCALE * __logf(1.f + sv.x);
        l1[j] = DB_SCALE * __logf(1.f + sv.y);
    }
    float* m0 = scatmap + (size_t)r0 * W_IMG + c0;
    float* m1 = m0 + W_IMG;
    ((float4*)m0)[0] = make_float4(l0[0], l0[1], l0[2], l0[3]);
    ((float4*)m0)[1] = make_float4(l0[4], l0[5], l0[6], l0[7]);
    ((float4*)m1)[0] = make_float4(l1[0], l1[1], l1[2], l1[3]);
    ((float4*)m1)[1] = make_float4(l1[4], l1[5], l1[6], l1[7]);
}

// ---------------------------------------------------------------------------
// Kernel 2: vertical 23-tap conv (reflect) + b_mode epilogue. Axial taps
// computed per-thread (23 expf ~ noise), normalized by their own sum.
// Streaming, smem-free: each thread owns a column pair (float2) and 16
// output rows; 38 fully unrolled coalesced float2 loads feed 16 packed
// accumulators (transposed-FIR form).
// ---------------------------------------------------------------------------
__global__ void __launch_bounds__(256)
k2_vconv(float* __restrict__ bmode, float* __restrict__ env,
         const float* __restrict__ ra_p) {
    int idx = blockIdx.x * 256 + threadIdx.x;
    int xp = idx & 1023;           // column pair
    int sy = idx >> 10;            // y strip (16 rows), 0..127
    int x  = xp * 2;
    int y0 = sy * 16;

    // axial taps, normalized
    float ra = ra_p[0];
    float tap[23];
    float sa = 0.f;
#pragma unroll
    for (int i = 0; i < 23; i++) {
        float p = (float)(i - 11) * (1.0f / 11.0f) * C_HALF_AX + ra * C_SH;
        float arg = 3.0f * (2.0f / C_TONE) * p;
        tap[i] = __expf(-0.5f * arg * arg);
        sa += tap[i];
    }
    float inv = 1.0f / sa;
    float2 cp[23];
#pragma unroll
    for (int i = 0; i < 23; i++) {
        float c = tap[i] * inv;
        cp[i] = make_float2(c, c);
    }

    float2 acc[16];
#pragma unroll
    for (int j = 0; j < 16; j++) acc[j] = make_float2(0.f, 0.f);

#pragma unroll
    for (int r = 0; r < 38; r++) {
        int y = reflect_idx(y0 - 11 + r, H_IMG);
        float2 v = *(const float2*)(g_tmp + (size_t)y * W_IMG + x);
        int jlo = (r > 22) ? (r - 22) : 0;
        int jhi = (r < 15) ? r : 15;
#pragma unroll
        for (int j = 0; j < 16; j++) {
            if (j >= jlo && j <= jhi) acc[j] = ffma2(cp[r - j], v, acc[j]);
        }
    }

#pragma unroll
    for (int j = 0; j < 16; j++) {
        size_t o = (size_t)(y0 + j) * W_IMG + x;
        *(float2*)(env + o) = acc[j];
        float2 b = make_float2(DB_SCALE * __logf(1.f + acc[j].x),
                               DB_SCALE * __logf(1.f + acc[j].y));
        *(float2*)(bmode + o) = b;
    }
}

// ---------------------------------------------------------------------------
extern "C" void kernel_launch(void* const* d_in, const int* in_sizes, int n_in,
                              void* d_out, int out_size) {
    const float* raw = (const float*)d_in[0];
    const float* ra  = (const float*)d_in[1];
    const float* rl  = (const float*)d_in[2];
    float* out     = (float*)d_out;
    float* bmode   = out;                 // [1,1,H,W]
    float* scatmap = out + NPIX;          // [1,1,H,W]
    float* env     = out + 2 * NPIX;      // [1,1,H,W]

    k1_fused<<<dim3(W_IMG / TW, H_IMG / TH), 512>>>(raw, scatmap, rl);
    // 1024 column-pairs x 128 strips = 131072 threads = 512 blocks of 256
    k2_vconv<<<512, 256>>>(bmode, env, ra);
}

// round 7
// speedup vs baseline: 1.6758x; 1.6758x over previous
#include <cuda_runtime.h>
#include <math.h>

#define W_IMG 2048
#define H_IMG 2048
#define NPIX (W_IMG * H_IMG)

// scratch (no cudaMalloc allowed)
__device__ float g_tmp[NPIX];     // after horizontal conv, [h][w]

#define DB_SCALE 8.6858896380650365530225783783321f  // 20/ln(10)

// static float constants (match reference float32 math)
#define C_HALF_AX  3.08e-4f
#define C_HALF_LAT 6.16e-4f
#define C_SH       (0.05f / 2048.0f)
#define C_SW       (0.04f / 2048.0f)
#define C_TONE     6.16e-4f
#define C_FWL      3.08e-4f
#define C_PI       3.14159265358979323846f

// ---- packed fp32x2 FMA (Blackwell) ------------------------------------
union F2U { float2 f; unsigned long long u; };

__device__ __forceinline__ float2 ffma2(float2 a, float2 b, float2 c) {
    F2U ua, ub, uc, ud;
    ua.f = a; ub.f = b; uc.f = c;
    asm("fma.rn.f32x2 %0, %1, %2, %3;"
        : "=l"(ud.u) : "l"(ua.u), "l"(ub.u), "l"(uc.u));
    return ud.f;
}

__device__ __forceinline__ int reflect_idx(int x, int n) {
    x = (x < 0) ? -x : x;
    return (x >= n) ? 2 * n - 2 - x : x;
}

// ---------------------------------------------------------------------------
// Kernel 1 (fused): scatterer = exp(raw[...,0]).T, horizontal 61-tap conv
// (reflect) -> g_tmp, scatterers_map = 20*log10(scat+1). Lateral taps
// computed per-block. Tile: 128 (w) x 32 (h), 256 threads.
// SMEM: row-pairs: s[(h>>1)*SROW + p*2 + (h&1)] -> float2 at column p holds
// rows (2*(h>>1), +1): aligned 8B operand for FFMA2.
// ---------------------------------------------------------------------------
#define TW 128
#define TH 32
#define SWT 188           // TW + 60 halo
#define SROW 378          // 2*SWT + 2 pad

__global__ void __launch_bounds__(256)
k1_fused(const float4* __restrict__ raw4, float* __restrict__ scatmap,
         const float* __restrict__ rl_p) {
    __shared__ float  s[16 * SROW];    // 16 row-pairs x 378 floats = 24.2KB
    __shared__ float2 sc[64];
    __shared__ float  tapraw[61];
    __shared__ float  s_inv;

    const int w0 = blockIdx.x * TW;
    const int h0 = blockIdx.y * TH;
    const int tid = threadIdx.x;

    // lateral taps (raw)
    if (tid < 61) {
        float rl = __ldg(rl_p);
        float q = ((float)(tid - 30) * (1.0f / 30.0f) * C_HALF_LAT + rl * C_SW)
                  / C_FWL;
        float x = C_PI * q;
        float si = (fabsf(x) < 1e-12f) ? 1.0f : sinf(x) / x;
        tapraw[tid] = si * si;
    }

    // load + exp (implicit transpose): lanes run along h, float4 loads
    for (int i = tid; i < SWT * TH; i += 256) {
        int p = i >> 5;                 // tile w index 0..187
        int h = i & 31;                 // local h
        int wg = reflect_idx(w0 + p - 30, W_IMG);
        float4 r4 = __ldg(raw4 + (size_t)wg * H_IMG + h0 + h);
        s[(h >> 1) * SROW + p * 2 + (h & 1)] = __expf(r4.x);
    }
    __syncthreads();

    if (tid == 0) {
        float sl = 0.f;
        for (int j = 0; j < 61; j++) sl += tapraw[j];
        s_inv = 1.0f / sl;
    }
    __syncthreads();
    if (tid < 64) {
        float c = (tid < 61) ? tapraw[tid] * s_inv : 0.f;
        sc[tid] = make_float2(c, c);
    }
    __syncthreads();

    // compute: thread -> (row-pair h2 = tid&15, column group wg = tid>>4)
    const int h2 = tid & 15;
    const int wg = tid >> 4;
    const float2* rowp = (const float2*)(s + h2 * SROW);
    const int base = wg * 8;           // first output column of this thread

    float2 win[8], acc[8];
#pragma unroll
    for (int j = 0; j < 8; j++) {
        win[j] = rowp[base + j];
        acc[j] = make_float2(0.f, 0.f);
    }
#pragma unroll
    for (int k = 0; k < 61; k++) {
        float2 cp = sc[k];
#pragma unroll
        for (int j = 0; j < 8; j++) acc[j] = ffma2(cp, win[j], acc[j]);
        if (k < 60) {
#pragma unroll
            for (int j = 0; j < 7; j++) win[j] = win[j + 1];
            win[7] = rowp[base + k + 8];   // max idx 187, safe
        }
    }

    // stores: conv result (2 rows x 8 cols)
    const int r0 = h0 + 2 * h2;
    const int c0 = w0 + base;
    float* t0 = g_tmp + (size_t)r0 * W_IMG + c0;
    float* t1 = t0 + W_IMG;
    ((float4*)t0)[0] = make_float4(acc[0].x, acc[1].x, acc[2].x, acc[3].x);
    ((float4*)t0)[1] = make_float4(acc[4].x, acc[5].x, acc[6].x, acc[7].x);
    ((float4*)t1)[0] = make_float4(acc[0].y, acc[1].y, acc[2].y, acc[3].y);
    ((float4*)t1)[1] = make_float4(acc[4].y, acc[5].y, acc[6].y, acc[7].y);

    // scatmap: scatterer at output column j = smem column base+j+30
    float l0[8], l1[8];
#pragma unroll
    for (int j = 0; j < 8; j++) {
        float2 sv = rowp[base + j + 30];
        l0[j] = DB_SCALE * __logf(1.f + sv.x);
        l1[j] = DB_SCALE * __logf(1.f + sv.y);
    }
    float* m0 = scatmap + (size_t)r0 * W_IMG + c0;
    float* m1 = m0 + W_IMG;
    ((float4*)m0)[0] = make_float4(l0[0], l0[1], l0[2], l0[3]);
    ((float4*)m0)[1] = make_float4(l0[4], l0[5], l0[6], l0[7]);
    ((float4*)m1)[0] = make_float4(l1[0], l1[1], l1[2], l1[3]);
    ((float4*)m1)[1] = make_float4(l1[4], l1[5], l1[6], l1[7]);
}

// ---------------------------------------------------------------------------
// Kernel 2: vertical 23-tap conv (reflect) + b_mode epilogue. Axial taps
// per-thread. Streaming, smem-free: each thread owns a column pair and an
// 8-row strip; 30 unrolled coalesced float2 loads feed 8 packed
// accumulators (transposed FIR). 1024 blocks (fixes R4's grid-limited
// 33.9% occupancy).
// ---------------------------------------------------------------------------
__global__ void __launch_bounds__(256)
k2_vconv(float* __restrict__ bmode, float* __restrict__ env,
         const float* __restrict__ ra_p) {
    const int idx = blockIdx.x * 256 + threadIdx.x;
    const int xp = idx & 1023;           // column pair
    const int sy = idx >> 10;            // y strip (8 rows), 0..255
    const int x  = xp * 2;
    const int y0 = sy * 8;

    // axial taps, normalized
    float ra = __ldg(ra_p);
    float tap[23];
    float sa = 0.f;
#pragma unroll
    for (int i = 0; i < 23; i++) {
        float p = (float)(i - 11) * (1.0f / 11.0f) * C_HALF_AX + ra * C_SH;
        float arg = 3.0f * (2.0f / C_TONE) * p;
        tap[i] = __expf(-0.5f * arg * arg);
        sa += tap[i];
    }
    float inv = 1.0f / sa;
    float2 cp[23];
#pragma unroll
    for (int i = 0; i < 23; i++) {
        float c = tap[i] * inv;
        cp[i] = make_float2(c, c);
    }

    float2 acc[8];
#pragma unroll
    for (int j = 0; j < 8; j++) acc[j] = make_float2(0.f, 0.f);

#pragma unroll
    for (int r = 0; r < 30; r++) {
        int y = reflect_idx(y0 - 11 + r, H_IMG);
        float2 v = *(const float2*)(g_tmp + (size_t)y * W_IMG + x);
        int jlo = (r > 22) ? (r - 22) : 0;
        int jhi = (r < 7) ? r : 7;
#pragma unroll
        for (int j = 0; j < 8; j++) {
            if (j >= jlo && j <= jhi) acc[j] = ffma2(cp[r - j], v, acc[j]);
        }
    }

#pragma unroll
    for (int j = 0; j < 8; j++) {
        size_t o = (size_t)(y0 + j) * W_IMG + x;
        *(float2*)(env + o) = acc[j];
        float2 b = make_float2(DB_SCALE * __logf(1.f + acc[j].x),
                               DB_SCALE * __logf(1.f + acc[j].y));
        *(float2*)(bmode + o) = b;
    }
}

// ---------------------------------------------------------------------------
extern "C" void kernel_launch(void* const* d_in, const int* in_sizes, int n_in,
                              void* d_out, int out_size) {
    const float4* raw4 = (const float4*)d_in[0];
    const float*  ra   = (const float*)d_in[1];
    const float*  rl   = (const float*)d_in[2];
    float* out     = (float*)d_out;
    float* bmode   = out;                 // [1,1,H,W]
    float* scatmap = out + NPIX;          // [1,1,H,W]
    float* env     = out + 2 * NPIX;      // [1,1,H,W]

    k1_fused<<<dim3(W_IMG / TW, H_IMG / TH), 256>>>(raw4, scatmap, rl);
    // 1024 col-pairs x 256 strips of 8 rows = 262144 threads = 1024 blocks
    k2_vconv<<<1024, 256>>>(bmode, env, ra);
}